// round 13
// baseline (speedup 1.0000x reference)
#include <cuda_runtime.h>
#include <cuda_bf16.h>
#include <cstdint>

// Problem constants: B=32, N=8192, C=512, K=128
#define PB    32
#define PN    8192
#define PC    512
#define PK    128
#define SEGS  32        // CTAs per batch
#define TPB   256       // threads per CTA = elements per CTA (SEGS*TPB = PN)
#define WORDS 256       // bitmask words per batch (PN/32)

// Scratch (zero-init at module load; finisher restores zeros every launch).
__device__ unsigned int g_mask[PB * WORDS];
__device__ unsigned int g_done[PB];

__global__ void __launch_bounds__(TPB) fused_filter_kernel(
    const float* __restrict__ one_hot,
    const int*   __restrict__ id_ptr,
    float*       __restrict__ out)
{
    const int g    = blockIdx.x;         // 0 .. PB*SEGS-1
    const int b    = g >> 5;             // batch
    const int seg  = g & (SEGS - 1);     // segment within batch
    const int t    = threadIdx.x;
    const int lane = t & 31;
    const int wid  = t >> 5;             // 0..7

    const int id = __ldg(id_ptr);
    const int n  = seg * TPB + t;        // position within batch
    const size_t idx = (size_t)b * PN + n;

    // ---- scattered gather with explicit L2 policy:
    //      evict_last  -> gathered lines persist in L2 across graph replays
    //      L2::64B     -> request reduced fetch granularity on miss
    float v;
    {
        const float* src = one_hot + idx * PC + id;
        unsigned long long pol;
        asm("createpolicy.fractional.L2::evict_last.b64 %0, 1.0;" : "=l"(pol));
        asm volatile("ld.global.L2::cache_hint.L2::64B.f32 %0, [%1], %2;"
                     : "=f"(v) : "l"(src), "l"(pol) : "memory");
    }

    // ---- block_id output (coalesced; never fenced) ----
    out[idx] = v;

    // ---- stage hit via bitmask atomic; consume return so the update is
    //      performed at L2 before this thread reaches the barrier.
    if (v != 0.0f) {
        unsigned old = atomicOr(&g_mask[b * WORDS + (n >> 5)], 1u << (n & 31));
        if (old == 0xFFFFFFFFu) out[idx] = v;   // impossible; consumes 'old'
    }

    __syncthreads();                      // all staging atomics complete (L2)

    __shared__ unsigned s_done;
    if (t == 0) s_done = atomicAdd(&g_done[b], 1u);
    __syncthreads();

    if (s_done != SEGS - 1) return;       // not the last CTA of this batch

    // ========== finisher CTA for batch b (wait-free: all others done) ======
    __threadfence();                      // acquire; single CTA, cheap

    // Each thread owns one 32-bit mask word = positions [t*32, t*32+32)
    unsigned w = __ldcg(&g_mask[b * WORDS + t]);
    int cnt = __popc(w);

    // Inclusive warp scan of per-word counts
    int inc = cnt;
#pragma unroll
    for (int d = 1; d < 32; d <<= 1) {
        int y = __shfl_up_sync(0xffffffffu, inc, d);
        if (lane >= d) inc += y;
    }

    __shared__ int s_wsum[8];
    if (lane == 31) s_wsum[wid] = inc;
    __syncthreads();

    if (wid == 0) {
        int wv = (lane < 8) ? s_wsum[lane] : 0;
        int winc = wv;
#pragma unroll
        for (int d = 1; d < 8; d <<= 1) {
            int y = __shfl_up_sync(0xffffffffu, winc, d);
            if (lane >= d) winc += y;
        }
        if (lane < 8) s_wsum[lane] = winc - wv;   // exclusive warp base
    }
    __syncthreads();

    int pos = s_wsum[wid] + (inc - cnt);          // exclusive thread base

    // Emit set-bit positions in ascending order (bitmask => sorted for free)
    float* oidx = out + (size_t)PB * PN + (size_t)b * PK;
    while (w) {
        int bit = __ffs(w) - 1;
        w &= w - 1;
        if (pos < PK) oidx[pos] = (float)(t * 32 + bit);
        pos++;
    }

    // ---- reset scratch for the next graph replay ----
    g_mask[b * WORDS + t] = 0u;
    if (t == 0) g_done[b] = 0u;
}

extern "C" void kernel_launch(void* const* d_in, const int* in_sizes, int n_in,
                              void* d_out, int out_size)
{
    const float* one_hot = (const float*)d_in[0];
    const int*   id_ptr  = (const int*)d_in[1];
    float*       out     = (float*)d_out;

    (void)in_sizes; (void)n_in; (void)out_size;

    fused_filter_kernel<<<PB * SEGS, TPB>>>(one_hot, id_ptr, out);
}

// round 14
// speedup vs baseline: 1.0294x; 1.0294x over previous
#include <cuda_runtime.h>
#include <cuda_bf16.h>
#include <cstdint>

// Problem constants: B=32, N=8192, C=512, K=128
#define PB    32
#define PN    8192
#define PC    512
#define PK    128
#define SEGS  32        // CTAs per batch (kernel 1)
#define TPB   256       // threads per CTA
#define WORDS 256       // bitmask words per batch (PN/32)

// Scratch (zero-init at module load; kernel 2 restores zeros every launch).
__device__ unsigned int g_mask[PB * WORDS];

// ---------------------------------------------------------------------------
// Kernel 1: pure gather. No barriers, no finisher, no atomic round-trips.
// CTAs retire as soon as their memory ops issue; nothing gates on other CTAs.
// ---------------------------------------------------------------------------
__global__ void __launch_bounds__(TPB) gather_kernel(
    const float* __restrict__ one_hot,
    const int*   __restrict__ id_ptr,
    float*       __restrict__ out)
{
    const int g = blockIdx.x;            // 0 .. PB*SEGS-1
    const int b = g >> 5;                // batch
    const int n = (g & (SEGS - 1)) * TPB + threadIdx.x;   // position in batch
    const size_t idx = (size_t)b * PN + n;

    const int id = __ldg(id_ptr);

    // Scattered gather: L2-only sector load (transaction count is the floor)
    float v = __ldcg(one_hot + idx * PC + id);

    // block_id output (coalesced)
    out[idx] = v;

    // Stage hit into per-batch bitmask via REDG (no return -> no wait).
    // Visibility to kernel 2 is guaranteed by the kernel boundary.
    if (v != 0.0f) {
        asm volatile("red.global.or.b32 [%0], %1;"
                     :: "l"(&g_mask[b * WORDS + (n >> 5)]), "r"(1u << (n & 31))
                     : "memory");
    }
}

// ---------------------------------------------------------------------------
// Kernel 2: one CTA per batch. Scan the bitmask (L2-hot, 1KB/batch), emit the
// K indices in ascending order, reset the mask for the next graph replay.
// ---------------------------------------------------------------------------
__global__ void __launch_bounds__(TPB) emit_kernel(float* __restrict__ out)
{
    const int b    = blockIdx.x;         // batch
    const int t    = threadIdx.x;        // 0..255, owns one mask word
    const int lane = t & 31;
    const int wid  = t >> 5;             // 0..7

    unsigned w = __ldcg(&g_mask[b * WORDS + t]);
    int cnt = __popc(w);

    // Inclusive warp scan of per-word counts
    int inc = cnt;
#pragma unroll
    for (int d = 1; d < 32; d <<= 1) {
        int y = __shfl_up_sync(0xffffffffu, inc, d);
        if (lane >= d) inc += y;
    }

    __shared__ int s_wsum[8];
    if (lane == 31) s_wsum[wid] = inc;
    __syncthreads();

    if (wid == 0) {
        int wv = (lane < 8) ? s_wsum[lane] : 0;
        int winc = wv;
#pragma unroll
        for (int d = 1; d < 8; d <<= 1) {
            int y = __shfl_up_sync(0xffffffffu, winc, d);
            if (lane >= d) winc += y;
        }
        if (lane < 8) s_wsum[lane] = winc - wv;   // exclusive warp base
    }
    __syncthreads();

    int pos = s_wsum[wid] + (inc - cnt);          // exclusive thread base

    // Emit set-bit positions in ascending order (bitmask => sorted for free)
    float* oidx = out + (size_t)PB * PN + (size_t)b * PK;
    while (w) {
        int bit = __ffs(w) - 1;
        w &= w - 1;
        if (pos < PK) oidx[pos] = (float)(t * 32 + bit);
        pos++;
    }

    // Reset scratch for the next graph replay
    g_mask[b * WORDS + t] = 0u;
}

extern "C" void kernel_launch(void* const* d_in, const int* in_sizes, int n_in,
                              void* d_out, int out_size)
{
    const float* one_hot = (const float*)d_in[0];
    const int*   id_ptr  = (const int*)d_in[1];
    float*       out     = (float*)d_out;

    (void)in_sizes; (void)n_in; (void)out_size;

    gather_kernel<<<PB * SEGS, TPB>>>(one_hot, id_ptr, out);
    emit_kernel<<<PB, TPB>>>(out);
}